// round 7
// baseline (speedup 1.0000x reference)
#include <cuda_runtime.h>
#include <math.h>

#define Bn 64
#define Dn 256
#define Hn 512
#define Rn 32
#define CLIPV 50.0f
#define TB1 16   // batches per fused-block

// Output layout (concatenation of the returned tuple, fp32):
//   v_new      [64,512]      @ 0
//   new_h      [64,512]      @ 32768
//   dU_new     [64,512,512]  @ 65536
//   new_trace_e[64,512]      @ 16842752
//   new_trace_E[64,512,512]  @ 16875520
#define OFF_V    ((size_t)0)
#define OFF_NH   ((size_t)32768)
#define OFF_DU   ((size_t)65536)
#define OFF_TEO  ((size_t)16842752)
#define OFF_TEE  ((size_t)16875520)

// Device-global scratch (allocation-free)
__device__ float g_up[Hn * Hn];
__device__ float g_lo[Hn * Hn];
__device__ float g_suMod[Bn];
__device__ float g_sE;
__device__ float g_omU;

__device__ __forceinline__ float sigmoidf_(float x) {
    return 1.0f / (1.0f + expf(-x));
}

// ---------------------------------------------------------------------------
// Prep kernel, 576 blocks x 128 threads, one short wave:
//   bx < 512 : clip bounds row i = bx (up/lo into device globals).
//   bx >= 512: mod[b] for b = bx-512, warp-per-gate-row with float4 loads.
// Runs before the fused kernel so g_up/g_lo/g_suMod/g_sE/g_omU are ready
// with no intra-kernel races.
// ---------------------------------------------------------------------------
__global__ __launch_bounds__(128) void prep_kernel(
    const float* __restrict__ h2h_w, const float* __restrict__ alpha,
    const float* __restrict__ x, const float* __restrict__ h,
    const float* __restrict__ x2h_w, const float* __restrict__ x2h_b,
    const float* __restrict__ h2h_b, const float* __restrict__ tau_U,
    const float* __restrict__ tau_E) {
    const int warp = threadIdx.x >> 5;
    const int lane = threadIdx.x & 31;

    if (blockIdx.x < Hn) {
        const int i  = blockIdx.x;
        const int j0 = threadIdx.x * 4;
        const float4 W = *(const float4*)(h2h_w + (size_t)i * Hn + j0);
        const float4 A = *(const float4*)(alpha + (size_t)i * Hn + j0);
        float4 up, lo;
        const float d0 = fmaxf(A.x, 0.f) + 1e-8f;
        const float d1 = fmaxf(A.y, 0.f) + 1e-8f;
        const float d2 = fmaxf(A.z, 0.f) + 1e-8f;
        const float d3 = fmaxf(A.w, 0.f) + 1e-8f;
        up.x = fmaxf(CLIPV - W.x, 0.f) / d0;  lo.x = -fmaxf(CLIPV + W.x, 0.f) / d0;
        up.y = fmaxf(CLIPV - W.y, 0.f) / d1;  lo.y = -fmaxf(CLIPV + W.y, 0.f) / d1;
        up.z = fmaxf(CLIPV - W.z, 0.f) / d2;  lo.z = -fmaxf(CLIPV + W.z, 0.f) / d2;
        up.w = fmaxf(CLIPV - W.w, 0.f) / d3;  lo.w = -fmaxf(CLIPV + W.w, 0.f) / d3;
        *(float4*)(g_up + (size_t)i * Hn + j0) = up;
        *(float4*)(g_lo + (size_t)i * Hn + j0) = lo;
        return;
    }

    // ---- mod part ----
    const int b = blockIdx.x - Hn;
    __shared__ float sm[4];
    const float4* xb = (const float4*)(x + (size_t)b * Dn);
    const float4* hb = (const float4*)(h + (size_t)b * Hn);

    float acc = 0.f;
#pragma unroll
    for (int t = 0; t < 8; t++) {
        const int r = warp + 4 * t;          // 4 warps x 8 rows = 32
        const int o = Hn + r;
        const float4* xw = (const float4*)(x2h_w + (size_t)o * Dn);
        const float4* hw = (const float4*)(h2h_w + (size_t)o * Hn);
        float s = 0.f;
#pragma unroll
        for (int c = 0; c < 2; c++) {
            const float4 W4 = xw[c * 32 + lane];
            const float4 V4 = xb[c * 32 + lane];
            s = fmaf(W4.x, V4.x, s); s = fmaf(W4.y, V4.y, s);
            s = fmaf(W4.z, V4.z, s); s = fmaf(W4.w, V4.w, s);
        }
#pragma unroll
        for (int c = 0; c < 4; c++) {
            const float4 W4 = hw[c * 32 + lane];
            const float4 V4 = hb[c * 32 + lane];
            s = fmaf(W4.x, V4.x, s); s = fmaf(W4.y, V4.y, s);
            s = fmaf(W4.z, V4.z, s); s = fmaf(W4.w, V4.w, s);
        }
#pragma unroll
        for (int off = 16; off; off >>= 1)
            s += __shfl_xor_sync(0xffffffffu, s, off);
        if (lane == 0) acc += fmaxf(s + x2h_b[o] + h2h_b[o], 0.f);
    }
    if (lane == 0) sm[warp] = acc;
    __syncthreads();
    if (threadIdx.x == 0) {
        const float m  = sm[0] + sm[1] + sm[2] + sm[3];
        const float sU = sigmoidf_(tau_U[0]);
        g_suMod[b] = sU * m;
        if (b == 0) {
            g_sE  = sigmoidf_(tau_E[0]);
            g_omU = 1.0f - sU;
        }
    }
}

// ---------------------------------------------------------------------------
// Fused kernel: 512 blocks (one wave @48KB smem, 4 blocks/SM), 128 threads.
// Warp owns row-index i for TB1=16 batches. Per row (b,i):
//   - load du[4] + tE[4] (16 independent lane loads)
//   - warp-local split-accumulator reduction -> butterfly (all lanes get dv)
//   - epilogue immediately: dU_new / trace_E_new streamed out, with du still
//     in registers (dU read from DRAM exactly ONCE for the whole problem).
// up/lo/trace_e row vectors come from L2 via __ldg (written by prep_kernel).
// No block barriers after staging; no inter-block dependencies.
// ---------------------------------------------------------------------------
__global__ __launch_bounds__(128) void p12_kernel(
    const float* __restrict__ x, const float* __restrict__ h,
    const float* __restrict__ v, const float* __restrict__ dU,
    const float* __restrict__ trace_e, const float* __restrict__ trace_E,
    const float* __restrict__ x2h_w, const float* __restrict__ x2h_b,
    const float* __restrict__ h2h_w, const float* __restrict__ h2h_b,
    const float* __restrict__ alpha, const float* __restrict__ tau_v,
    const float* __restrict__ tau_e, float* __restrict__ out) {
    const int warp = threadIdx.x >> 5;
    const int lane = threadIdx.x & 31;
    const int gx = blockIdx.x & 127;
    const int gy = blockIdx.x >> 7;
    const int i  = gx * 4 + warp;
    const int b0 = gy * TB1;
    const int jb = lane * 4;

    __shared__ float sh_h[TB1][Hn];
    __shared__ float sh_x[TB1][Dn];

    for (int idx = threadIdx.x; idx < TB1 * (Hn / 4); idx += 128) {
        const int bb = idx >> 7;
        const int jj = (idx & 127) * 4;
        *(float4*)&sh_h[bb][jj] = *(const float4*)(h + (size_t)(b0 + bb) * Hn + jj);
    }
    for (int idx = threadIdx.x; idx < TB1 * (Dn / 4); idx += 128) {
        const int bb = idx >> 6;
        const int jj = (idx & 63) * 4;
        *(float4*)&sh_x[bb][jj] = *(const float4*)(x + (size_t)(b0 + bb) * Dn + jj);
    }
    __syncthreads();

    // Per-i rows in registers
    float ar[4][4], Wr[4][4];
#pragma unroll
    for (int c = 0; c < 4; c++) {
        const int j = c * 128 + jb;
        const float4 A = *(const float4*)(alpha + (size_t)i * Hn + j);
        const float4 W = *(const float4*)(h2h_w + (size_t)i * Hn + j);
        ar[c][0] = fmaxf(A.x, 0.f); ar[c][1] = fmaxf(A.y, 0.f);
        ar[c][2] = fmaxf(A.z, 0.f); ar[c][3] = fmaxf(A.w, 0.f);
        Wr[c][0] = W.x; Wr[c][1] = W.y; Wr[c][2] = W.z; Wr[c][3] = W.w;
    }
    float xw[2][4];
#pragma unroll
    for (int c = 0; c < 2; c++) {
        const float4 X = *(const float4*)(x2h_w + (size_t)i * Dn + c * 128 + jb);
        xw[c][0] = X.x; xw[c][1] = X.y; xw[c][2] = X.z; xw[c][3] = X.w;
    }
    const float bias = x2h_b[i] + h2h_b[i];
    const float sv   = sigmoidf_(tau_v[i]);
    const float se   = sigmoidf_(tau_e[i]);
    const float sE   = g_sE;
    const float omU  = g_omU;

    const float4* tE4base = (const float4*)trace_E;
    const float4* dU4base = (const float4*)dU;
    const float4* te4base = (const float4*)trace_e;
    const float4* up4base = (const float4*)g_up;
    const float4* lo4base = (const float4*)g_lo;
    float4* outDU4 = (float4*)(out + OFF_DU);
    float4* outTE4 = (float4*)(out + OFF_TEE);

    for (int bb = 0; bb < TB1; bb++) {
        const int b = b0 + bb;
        const size_t row4 = ((size_t)b * Hn + i) * 128;   // float4 row base

        // 8 independent stream loads (du kept in regs through the epilogue)
        float4 du[4], tE[4];
#pragma unroll
        for (int c = 0; c < 4; c++) {
            du[c] = dU4base[row4 + c * 32 + lane];
            tE[c] = __ldcs(&tE4base[row4 + c * 32 + lane]);
        }

        // split-accumulator reduction (short dependency chains)
        float p0 = 0.f, p1 = 0.f, p2 = 0.f, p3 = 0.f;
#pragma unroll
        for (int c = 0; c < 4; c++) {
            const int j = c * 128 + jb;
            const float* dp = (const float*)&du[c];
            const float4 H4 = *(const float4*)&sh_h[bb][j];
            p0 = fmaf(fmaf(ar[c][0], dp[0], Wr[c][0]), H4.x, p0);
            p1 = fmaf(fmaf(ar[c][1], dp[1], Wr[c][1]), H4.y, p1);
            p2 = fmaf(fmaf(ar[c][2], dp[2], Wr[c][2]), H4.z, p2);
            p3 = fmaf(fmaf(ar[c][3], dp[3], Wr[c][3]), H4.w, p3);
        }
#pragma unroll
        for (int c = 0; c < 2; c++) {
            const float4 X4 = *(const float4*)&sh_x[bb][c * 128 + jb];
            p0 = fmaf(xw[c][0], X4.x, p0);
            p1 = fmaf(xw[c][1], X4.y, p1);
            p2 = fmaf(xw[c][2], X4.z, p2);
            p3 = fmaf(xw[c][3], X4.w, p3);
        }
        float p = (p0 + p1) + (p2 + p3);
#pragma unroll
        for (int off = 16; off; off >>= 1)
            p += __shfl_xor_sync(0xffffffffu, p, off);
        // butterfly -> all lanes hold the full sum

        const float dv  = p + bias;
        const float vb  = __ldg(v + (size_t)b * Hn + i);
        const float vn  = fmaf(sv, dv - vb, vb);
        const float nh  = fmaxf(vn, 0.f);
        const float teS = __ldg(trace_e + (size_t)b * Hn + i);
        const float nte = fmaf(se, sh_h[bb][i] - teS, teS);
        const float suMod = g_suMod[b];
        if (lane == 0) {
            out[OFF_V   + (size_t)b * Hn + i] = vn;
            out[OFF_NH  + (size_t)b * Hn + i] = nh;
            out[OFF_TEO + (size_t)b * Hn + i] = nte;
        }

        // epilogue: stream out the two HxH rows
#pragma unroll
        for (int c = 0; c < 4; c++) {
            const int j = c * 128 + jb;
            const float4 te = __ldg(&te4base[((size_t)b << 7) + c * 32 + lane]);
            const float4 up = __ldg(&up4base[((size_t)i << 7) + c * 32 + lane]);
            const float4 lo = __ldg(&lo4base[((size_t)i << 7) + c * 32 + lane]);
            const float4 H4 = *(const float4*)&sh_h[bb][j];
            const float* dp = (const float*)&du[c];
            const float* tp = (const float*)&tE[c];

            float4 tOut, dOut;
            {
                const float o = nh * te.x - nte * H4.x;
                tOut.x = fmaf(sE, o - tp[0], tp[0]);
                dOut.x = fmaxf(fminf(fmaf(suMod, tOut.x, omU * dp[0]), up.x), lo.x);
            }
            {
                const float o = nh * te.y - nte * H4.y;
                tOut.y = fmaf(sE, o - tp[1], tp[1]);
                dOut.y = fmaxf(fminf(fmaf(suMod, tOut.y, omU * dp[1]), up.y), lo.y);
            }
            {
                const float o = nh * te.z - nte * H4.z;
                tOut.z = fmaf(sE, o - tp[2], tp[2]);
                dOut.z = fmaxf(fminf(fmaf(suMod, tOut.z, omU * dp[2]), up.z), lo.z);
            }
            {
                const float o = nh * te.w - nte * H4.w;
                tOut.w = fmaf(sE, o - tp[3], tp[3]);
                dOut.w = fmaxf(fminf(fmaf(suMod, tOut.w, omU * dp[3]), up.w), lo.w);
            }
            __stcs(&outTE4[row4 + c * 32 + lane], tOut);
            __stcs(&outDU4[row4 + c * 32 + lane], dOut);
        }
    }
}

extern "C" void kernel_launch(void* const* d_in, const int* in_sizes, int n_in,
                              void* d_out, int out_size) {
    const float* x       = (const float*)d_in[0];
    const float* h       = (const float*)d_in[1];
    const float* v       = (const float*)d_in[2];
    const float* dU      = (const float*)d_in[3];
    const float* trace_e = (const float*)d_in[4];
    const float* trace_E = (const float*)d_in[5];
    const float* x2h_w   = (const float*)d_in[6];
    const float* x2h_b   = (const float*)d_in[7];
    const float* h2h_w   = (const float*)d_in[8];
    const float* h2h_b   = (const float*)d_in[9];
    const float* alpha   = (const float*)d_in[10];
    const float* tau_v   = (const float*)d_in[11];
    const float* tau_e   = (const float*)d_in[12];
    const float* tau_U   = (const float*)d_in[13];
    const float* tau_E   = (const float*)d_in[14];
    float* out = (float*)d_out;

    prep_kernel<<<Hn + Bn, 128>>>(h2h_w, alpha, x, h, x2h_w, x2h_b, h2h_b,
                                  tau_U, tau_E);
    p12_kernel<<<512, 128>>>(x, h, v, dU, trace_e, trace_E, x2h_w, x2h_b,
                             h2h_w, h2h_b, alpha, tau_v, tau_e, out);
}

// round 8
// speedup vs baseline: 1.1050x; 1.1050x over previous
#include <cuda_runtime.h>
#include <math.h>

#define Bn 64
#define Dn 256
#define Hn 512
#define Rn 32
#define CLIPV 50.0f
#define TB1 16   // batches per P1 main block

// Output layout (concatenation of the returned tuple, fp32):
//   v_new      [64,512]      @ 0
//   new_h      [64,512]      @ 32768
//   dU_new     [64,512,512]  @ 65536
//   new_trace_e[64,512]      @ 16842752
//   new_trace_E[64,512,512]  @ 16875520
#define OFF_V    ((size_t)0)
#define OFF_NH   ((size_t)32768)
#define OFF_DU   ((size_t)65536)
#define OFF_TEO  ((size_t)16842752)
#define OFF_TEE  ((size_t)16875520)

// Device-global scratch (allocation-free)
__device__ float g_up[Hn * Hn];
__device__ float g_lo[Hn * Hn];
__device__ float g_suMod[Bn];
__device__ float g_sE;
__device__ float g_omU;

__device__ __forceinline__ float sigmoidf_(float x) {
    return 1.0f / (1.0f + expf(-x));
}

// ---------------------------------------------------------------------------
// P1: 1D grid of 576 blocks (one wave: 152 SMs x >=4 blocks @48KB smem).
//  bx < 512 : main slice, warp-per-(i,b) row reduction over dU, SOFTWARE
//             PIPELINED: row bb+1's dU loads + v/trace_e scalars issue
//             before row bb's butterfly, hiding the shuffle/store tail.
//             gy==0 blocks also fold in the clip-bound precompute.
//  bx >= 512: mod slice for b = bx - 512 (runs inside the main wave, free).
// ---------------------------------------------------------------------------
__global__ __launch_bounds__(128) void p1_kernel(
    const float* __restrict__ x, const float* __restrict__ h,
    const float* __restrict__ v, const float* __restrict__ dU,
    const float* __restrict__ trace_e, const float* __restrict__ x2h_w,
    const float* __restrict__ x2h_b, const float* __restrict__ h2h_w,
    const float* __restrict__ h2h_b, const float* __restrict__ alpha,
    const float* __restrict__ tau_v, const float* __restrict__ tau_e,
    const float* __restrict__ tau_U, const float* __restrict__ tau_E,
    float* __restrict__ out) {
    const int warp = threadIdx.x >> 5;
    const int lane = threadIdx.x & 31;

    __shared__ float sh_h[TB1][Hn];
    __shared__ float sh_x[TB1][Dn];

    if (blockIdx.x >= 512) {
        // ---- mod slice ----
        const int b = blockIdx.x - 512;
        float* sm = &sh_h[0][0];

        const float4* xb = (const float4*)(x + (size_t)b * Dn);
        const float4* hb = (const float4*)(h + (size_t)b * Hn);

        float acc = 0.f;
#pragma unroll
        for (int t = 0; t < 8; t++) {
            const int r = warp + 4 * t;
            const int o = Hn + r;
            const float4* xw = (const float4*)(x2h_w + (size_t)o * Dn);
            const float4* hw = (const float4*)(h2h_w + (size_t)o * Hn);
            float s = 0.f;
#pragma unroll
            for (int c = 0; c < 2; c++) {
                const float4 W4 = xw[c * 32 + lane];
                const float4 V4 = xb[c * 32 + lane];
                s = fmaf(W4.x, V4.x, s); s = fmaf(W4.y, V4.y, s);
                s = fmaf(W4.z, V4.z, s); s = fmaf(W4.w, V4.w, s);
            }
#pragma unroll
            for (int c = 0; c < 4; c++) {
                const float4 W4 = hw[c * 32 + lane];
                const float4 V4 = hb[c * 32 + lane];
                s = fmaf(W4.x, V4.x, s); s = fmaf(W4.y, V4.y, s);
                s = fmaf(W4.z, V4.z, s); s = fmaf(W4.w, V4.w, s);
            }
#pragma unroll
            for (int off = 16; off; off >>= 1)
                s += __shfl_xor_sync(0xffffffffu, s, off);
            if (lane == 0) acc += fmaxf(s + x2h_b[o] + h2h_b[o], 0.f);
        }
        if (lane == 0) sm[warp] = acc;
        __syncthreads();
        if (threadIdx.x == 0) {
            const float m  = sm[0] + sm[1] + sm[2] + sm[3];
            const float sU = sigmoidf_(tau_U[0]);
            g_suMod[b] = sU * m;
            if (b == 0) {
                g_sE  = sigmoidf_(tau_E[0]);
                g_omU = 1.0f - sU;
            }
        }
        return;
    }

    // ---- main reduction slice ----
    const int gx = blockIdx.x & 127;
    const int gy = blockIdx.x >> 7;
    const int i  = gx * 4 + warp;
    const int b0 = gy * TB1;
    const int jb = lane * 4;

    for (int idx = threadIdx.x; idx < TB1 * (Hn / 4); idx += 128) {
        const int bb = idx >> 7;
        const int jj = (idx & 127) * 4;
        *(float4*)&sh_h[bb][jj] = *(const float4*)(h + (size_t)(b0 + bb) * Hn + jj);
    }
    for (int idx = threadIdx.x; idx < TB1 * (Dn / 4); idx += 128) {
        const int bb = idx >> 6;
        const int jj = (idx & 63) * 4;
        *(float4*)&sh_x[bb][jj] = *(const float4*)(x + (size_t)(b0 + bb) * Dn + jj);
    }
    __syncthreads();

    // Per-i rows in registers (lane covers 4 chunks of 4 cols)
    float ar[4][4], Wr[4][4];
#pragma unroll
    for (int c = 0; c < 4; c++) {
        const int j = c * 128 + jb;
        const float4 A = *(const float4*)(alpha + (size_t)i * Hn + j);
        const float4 W = *(const float4*)(h2h_w + (size_t)i * Hn + j);
        ar[c][0] = fmaxf(A.x, 0.f); ar[c][1] = fmaxf(A.y, 0.f);
        ar[c][2] = fmaxf(A.z, 0.f); ar[c][3] = fmaxf(A.w, 0.f);
        Wr[c][0] = W.x; Wr[c][1] = W.y; Wr[c][2] = W.z; Wr[c][3] = W.w;
    }

    // Clip-bound fold: one block column computes up/lo.
    if (gy == 0) {
#pragma unroll
        for (int c = 0; c < 4; c++) {
            const int j = c * 128 + jb;
            float4 up, lo;
            float* u = (float*)&up;
            float* l = (float*)&lo;
#pragma unroll
            for (int k = 0; k < 4; k++) {
                const float d = ar[c][k] + 1e-8f;
                u[k] =  fmaxf(CLIPV - Wr[c][k], 0.f) / d;
                l[k] = -fmaxf(CLIPV + Wr[c][k], 0.f) / d;
            }
            *(float4*)(g_up + (size_t)i * Hn + j) = up;
            *(float4*)(g_lo + (size_t)i * Hn + j) = lo;
        }
    }

    float xw[2][4];
#pragma unroll
    for (int c = 0; c < 2; c++) {
        const float4 X = *(const float4*)(x2h_w + (size_t)i * Dn + c * 128 + jb);
        xw[c][0] = X.x; xw[c][1] = X.y; xw[c][2] = X.z; xw[c][3] = X.w;
    }
    const float bias = x2h_b[i] + h2h_b[i];
    const float sv   = sigmoidf_(tau_v[i]);
    const float se   = sigmoidf_(tau_e[i]);

    const float4* dU4 = (const float4*)dU;
    size_t row4 = ((size_t)b0 * Hn + i) * 128;   // float4 row base

    // ---- software pipeline: prime row bb=0 ----
    float4 pd0 = dU4[row4 + 0 * 32 + lane];
    float4 pd1 = dU4[row4 + 1 * 32 + lane];
    float4 pd2 = dU4[row4 + 2 * 32 + lane];
    float4 pd3 = dU4[row4 + 3 * 32 + lane];
    float vb  = __ldg(v + (size_t)b0 * Hn + i);
    float teS = __ldg(trace_e + (size_t)b0 * Hn + i);

    for (int bb = 0; bb < TB1; bb++) {
        const int b = b0 + bb;
        const float4 d0 = pd0, d1 = pd1, d2 = pd2, d3 = pd3;
        const size_t nrow4 = row4 + (size_t)Hn * 128;

        float vbn = 0.f, teSn = 0.f;
        if (bb + 1 < TB1) {
            // next row's loads issue BEFORE this row's butterfly
            pd0 = dU4[nrow4 + 0 * 32 + lane];
            pd1 = dU4[nrow4 + 1 * 32 + lane];
            pd2 = dU4[nrow4 + 2 * 32 + lane];
            pd3 = dU4[nrow4 + 3 * 32 + lane];
            vbn  = __ldg(v + (size_t)(b + 1) * Hn + i);
            teSn = __ldg(trace_e + (size_t)(b + 1) * Hn + i);
        }

        // split-accumulator reduction on the current row
        float p0 = 0.f, p1 = 0.f, p2 = 0.f, p3 = 0.f;
        {
            const float* dp;
            const float4* Hrow;
            dp = (const float*)&d0; Hrow = (const float4*)&sh_h[bb][0 * 128 + jb];
            { const float4 H4 = *Hrow;
              p0 = fmaf(fmaf(ar[0][0], dp[0], Wr[0][0]), H4.x, p0);
              p1 = fmaf(fmaf(ar[0][1], dp[1], Wr[0][1]), H4.y, p1);
              p2 = fmaf(fmaf(ar[0][2], dp[2], Wr[0][2]), H4.z, p2);
              p3 = fmaf(fmaf(ar[0][3], dp[3], Wr[0][3]), H4.w, p3); }
            dp = (const float*)&d1; Hrow = (const float4*)&sh_h[bb][1 * 128 + jb];
            { const float4 H4 = *Hrow;
              p0 = fmaf(fmaf(ar[1][0], dp[0], Wr[1][0]), H4.x, p0);
              p1 = fmaf(fmaf(ar[1][1], dp[1], Wr[1][1]), H4.y, p1);
              p2 = fmaf(fmaf(ar[1][2], dp[2], Wr[1][2]), H4.z, p2);
              p3 = fmaf(fmaf(ar[1][3], dp[3], Wr[1][3]), H4.w, p3); }
            dp = (const float*)&d2; Hrow = (const float4*)&sh_h[bb][2 * 128 + jb];
            { const float4 H4 = *Hrow;
              p0 = fmaf(fmaf(ar[2][0], dp[0], Wr[2][0]), H4.x, p0);
              p1 = fmaf(fmaf(ar[2][1], dp[1], Wr[2][1]), H4.y, p1);
              p2 = fmaf(fmaf(ar[2][2], dp[2], Wr[2][2]), H4.z, p2);
              p3 = fmaf(fmaf(ar[2][3], dp[3], Wr[2][3]), H4.w, p3); }
            dp = (const float*)&d3; Hrow = (const float4*)&sh_h[bb][3 * 128 + jb];
            { const float4 H4 = *Hrow;
              p0 = fmaf(fmaf(ar[3][0], dp[0], Wr[3][0]), H4.x, p0);
              p1 = fmaf(fmaf(ar[3][1], dp[1], Wr[3][1]), H4.y, p1);
              p2 = fmaf(fmaf(ar[3][2], dp[2], Wr[3][2]), H4.z, p2);
              p3 = fmaf(fmaf(ar[3][3], dp[3], Wr[3][3]), H4.w, p3); }
        }
#pragma unroll
        for (int c = 0; c < 2; c++) {
            const float4 X4 = *(const float4*)&sh_x[bb][c * 128 + jb];
            p0 = fmaf(xw[c][0], X4.x, p0);
            p1 = fmaf(xw[c][1], X4.y, p1);
            p2 = fmaf(xw[c][2], X4.z, p2);
            p3 = fmaf(xw[c][3], X4.w, p3);
        }
        float p = (p0 + p1) + (p2 + p3);
#pragma unroll
        for (int off = 16; off; off >>= 1)
            p += __shfl_xor_sync(0xffffffffu, p, off);

        if (lane == 0) {
            const float dv  = p + bias;
            const float vn  = fmaf(sv, dv - vb, vb);
            const float nte = fmaf(se, sh_h[bb][i] - teS, teS);
            out[OFF_V   + (size_t)b * Hn + i] = vn;
            out[OFF_NH  + (size_t)b * Hn + i] = fmaxf(vn, 0.f);
            out[OFF_TEO + (size_t)b * Hn + i] = nte;
        }

        vb = vbn; teS = teSn;
        row4 = nrow4;
    }
}

// ---------------------------------------------------------------------------
// P2: pure streaming elementwise pass over the HxH matrices.
// 4 independent tasks per thread (quarter-stride) for deeper MLP.
// trace_E via __ldcs (zero reuse); outputs via __stcs.
// ---------------------------------------------------------------------------
#define P2_BLOCKS 4096
#define P2_THREADS 256
#define P2_TOTAL  ((size_t)Bn * Hn * 128)
#define P2_QTR    (P2_TOTAL / 4)

__global__ __launch_bounds__(P2_THREADS) void p2_kernel(
    const float* __restrict__ dU, const float* __restrict__ trace_E,
    const float* __restrict__ h, const float* __restrict__ trace_e,
    float* __restrict__ out) {
    const size_t gid = (size_t)blockIdx.x * P2_THREADS + threadIdx.x;
    const float sE  = g_sE;
    const float omU = g_omU;

    const float4* dU4 = (const float4*)dU;
    const float4* tE4 = (const float4*)trace_E;
    const float4* h4p = (const float4*)h;
    const float4* te4p = (const float4*)trace_e;
    const float4* up4 = (const float4*)g_up;
    const float4* lo4 = (const float4*)g_lo;
    float4* outDU = (float4*)(out + OFF_DU);
    float4* outTE = (float4*)(out + OFF_TEE);

#pragma unroll
    for (int q = 0; q < 4; q++) {
        const size_t t = gid + (size_t)q * P2_QTR;
        const int j4  = (int)(t & 127);
        const size_t row = t >> 7;           // b*512 + i
        const int i = (int)(row & 511);
        const int b = (int)(row >> 9);

        const float4 du = dU4[t];
        const float4 tE = __ldcs(&tE4[t]);
        const float4 hh = h4p[((size_t)b << 7) + j4];
        const float4 te = te4p[((size_t)b << 7) + j4];
        const float4 up = up4[((size_t)i << 7) + j4];
        const float4 lo = lo4[((size_t)i << 7) + j4];
        const float nh  = __ldg(out + OFF_NH  + row);
        const float nte = __ldg(out + OFF_TEO + row);
        const float suMod = g_suMod[b];

        float4 tOut, dOut;
        {
            const float o = nh * te.x - nte * hh.x;
            tOut.x = fmaf(sE, o - tE.x, tE.x);
            dOut.x = fmaxf(fminf(fmaf(suMod, tOut.x, omU * du.x), up.x), lo.x);
        }
        {
            const float o = nh * te.y - nte * hh.y;
            tOut.y = fmaf(sE, o - tE.y, tE.y);
            dOut.y = fmaxf(fminf(fmaf(suMod, tOut.y, omU * du.y), up.y), lo.y);
        }
        {
            const float o = nh * te.z - nte * hh.z;
            tOut.z = fmaf(sE, o - tE.z, tE.z);
            dOut.z = fmaxf(fminf(fmaf(suMod, tOut.z, omU * du.z), up.z), lo.z);
        }
        {
            const float o = nh * te.w - nte * hh.w;
            tOut.w = fmaf(sE, o - tE.w, tE.w);
            dOut.w = fmaxf(fminf(fmaf(suMod, tOut.w, omU * du.w), up.w), lo.w);
        }
        __stcs(&outTE[t], tOut);
        __stcs(&outDU[t], dOut);
    }
}

extern "C" void kernel_launch(void* const* d_in, const int* in_sizes, int n_in,
                              void* d_out, int out_size) {
    const float* x       = (const float*)d_in[0];
    const float* h       = (const float*)d_in[1];
    const float* v       = (const float*)d_in[2];
    const float* dU      = (const float*)d_in[3];
    const float* trace_e = (const float*)d_in[4];
    const float* trace_E = (const float*)d_in[5];
    const float* x2h_w   = (const float*)d_in[6];
    const float* x2h_b   = (const float*)d_in[7];
    const float* h2h_w   = (const float*)d_in[8];
    const float* h2h_b   = (const float*)d_in[9];
    const float* alpha   = (const float*)d_in[10];
    const float* tau_v   = (const float*)d_in[11];
    const float* tau_e   = (const float*)d_in[12];
    const float* tau_U   = (const float*)d_in[13];
    const float* tau_E   = (const float*)d_in[14];
    float* out = (float*)d_out;

    p1_kernel<<<576, 128>>>(x, h, v, dU, trace_e, x2h_w, x2h_b, h2h_w, h2h_b,
                            alpha, tau_v, tau_e, tau_U, tau_E, out);
    p2_kernel<<<P2_BLOCKS, P2_THREADS>>>(dU, trace_E, h, trace_e, out);
}

// round 10
// speedup vs baseline: 1.1423x; 1.0337x over previous
#include <cuda_runtime.h>
#include <math.h>
#include <stdint.h>

#define Bn 64
#define Dn 256
#define Hn 512
#define Rn 32
#define CLIPV 50.0f
#define TB1 16   // batches per P1 main block

// Output layout (concatenation of the returned tuple, fp32):
//   v_new      [64,512]      @ 0
//   new_h      [64,512]      @ 32768
//   dU_new     [64,512,512]  @ 65536
//   new_trace_e[64,512]      @ 16842752
//   new_trace_E[64,512,512]  @ 16875520
#define OFF_V    ((size_t)0)
#define OFF_NH   ((size_t)32768)
#define OFF_DU   ((size_t)65536)
#define OFF_TEO  ((size_t)16842752)
#define OFF_TEE  ((size_t)16875520)

// Device-global scratch (allocation-free)
__device__ float g_up[Hn * Hn];
__device__ float g_lo[Hn * Hn];
__device__ float g_suMod[Bn];
__device__ float g_sE;
__device__ float g_omU;

__device__ __forceinline__ float sigmoidf_(float x) {
    return 1.0f / (1.0f + expf(-x));
}

__device__ __forceinline__ void cp_async16(uint32_t saddr, const float* gaddr) {
    asm volatile("cp.async.cg.shared.global [%0], [%1], 16;\n"
                 :: "r"(saddr), "l"(gaddr) : "memory");
}
__device__ __forceinline__ void cp_commit() {
    asm volatile("cp.async.commit_group;\n" ::: "memory");
}
__device__ __forceinline__ void cp_wait1() {
    asm volatile("cp.async.wait_group 1;\n" ::: "memory");
}

// ---------------------------------------------------------------------------
// P1: 576 blocks x 128 threads, dynamic smem 48KB -> 4 blocks/SM, ONE wave.
// Dynamic smem layout (floats):
//   [0, 4096)      : dU tiles, per warp two 512-float buffers (double buffer)
//   [4096, 12288)  : sh_h[16][512]
//  bx < 512 : main slice. Warp-per-i, TB1=16 rows. dU rows streamed with
//             cp.async double-buffering (fire-and-forget: no register
//             scoreboard stalls). Refill of a buffer is issued only AFTER
//             the butterfly that data-depends on its previous contents,
//             so the WAR hazard on the double buffer cannot occur.
//             gy==0 blocks also fold in the clip-bound precompute.
//  bx >= 512: mod slice for b = bx - 512 (free, inside the main wave).
// ---------------------------------------------------------------------------
__global__ __launch_bounds__(128) void p1_kernel(
    const float* __restrict__ x, const float* __restrict__ h,
    const float* __restrict__ v, const float* __restrict__ dU,
    const float* __restrict__ trace_e, const float* __restrict__ x2h_w,
    const float* __restrict__ x2h_b, const float* __restrict__ h2h_w,
    const float* __restrict__ h2h_b, const float* __restrict__ alpha,
    const float* __restrict__ tau_v, const float* __restrict__ tau_e,
    const float* __restrict__ tau_U, const float* __restrict__ tau_E,
    float* __restrict__ out) {
    extern __shared__ float smem[];
    const int warp = threadIdx.x >> 5;
    const int lane = threadIdx.x & 31;

    if (blockIdx.x >= 512) {
        // ---- mod slice ----
        const int b = blockIdx.x - 512;
        float* sm = smem;  // 4 floats of scratch

        const float4* xb = (const float4*)(x + (size_t)b * Dn);
        const float4* hb = (const float4*)(h + (size_t)b * Hn);

        float acc = 0.f;
#pragma unroll
        for (int t = 0; t < 8; t++) {
            const int r = warp + 4 * t;
            const int o = Hn + r;
            const float4* xw = (const float4*)(x2h_w + (size_t)o * Dn);
            const float4* hw = (const float4*)(h2h_w + (size_t)o * Hn);
            float s = 0.f;
#pragma unroll
            for (int c = 0; c < 2; c++) {
                const float4 W4 = xw[c * 32 + lane];
                const float4 V4 = xb[c * 32 + lane];
                s = fmaf(W4.x, V4.x, s); s = fmaf(W4.y, V4.y, s);
                s = fmaf(W4.z, V4.z, s); s = fmaf(W4.w, V4.w, s);
            }
#pragma unroll
            for (int c = 0; c < 4; c++) {
                const float4 W4 = hw[c * 32 + lane];
                const float4 V4 = hb[c * 32 + lane];
                s = fmaf(W4.x, V4.x, s); s = fmaf(W4.y, V4.y, s);
                s = fmaf(W4.z, V4.z, s); s = fmaf(W4.w, V4.w, s);
            }
#pragma unroll
            for (int off = 16; off; off >>= 1)
                s += __shfl_xor_sync(0xffffffffu, s, off);
            if (lane == 0) acc += fmaxf(s + x2h_b[o] + h2h_b[o], 0.f);
        }
        if (lane == 0) sm[warp] = acc;
        __syncthreads();
        if (threadIdx.x == 0) {
            const float m  = sm[0] + sm[1] + sm[2] + sm[3];
            const float sU = sigmoidf_(tau_U[0]);
            g_suMod[b] = sU * m;
            if (b == 0) {
                g_sE  = sigmoidf_(tau_E[0]);
                g_omU = 1.0f - sU;
            }
        }
        return;
    }

    // ---- main reduction slice ----
    float* du_tiles = smem;                       // 4096 floats
    float (*sh_h)[Hn] = (float (*)[Hn])(smem + 4096);

    const int gx = blockIdx.x & 127;
    const int gy = blockIdx.x >> 7;
    const int i  = gx * 4 + warp;
    const int b0 = gy * TB1;
    const int jb = lane * 4;

    for (int idx = threadIdx.x; idx < TB1 * (Hn / 4); idx += 128) {
        const int bb = idx >> 7;
        const int jj = (idx & 127) * 4;
        *(float4*)&sh_h[bb][jj] = *(const float4*)(h + (size_t)(b0 + bb) * Hn + jj);
    }
    __syncthreads();

    // Per-i rows in registers (lane covers 4 chunks of 4 cols)
    float ar[4][4], Wr[4][4];
#pragma unroll
    for (int c = 0; c < 4; c++) {
        const int j = c * 128 + jb;
        const float4 A = *(const float4*)(alpha + (size_t)i * Hn + j);
        const float4 W = *(const float4*)(h2h_w + (size_t)i * Hn + j);
        ar[c][0] = fmaxf(A.x, 0.f); ar[c][1] = fmaxf(A.y, 0.f);
        ar[c][2] = fmaxf(A.z, 0.f); ar[c][3] = fmaxf(A.w, 0.f);
        Wr[c][0] = W.x; Wr[c][1] = W.y; Wr[c][2] = W.z; Wr[c][3] = W.w;
    }

    // Clip-bound fold: one block column computes up/lo.
    if (gy == 0) {
#pragma unroll
        for (int c = 0; c < 4; c++) {
            const int j = c * 128 + jb;
            float4 up, lo;
            float* u = (float*)&up;
            float* l = (float*)&lo;
#pragma unroll
            for (int k = 0; k < 4; k++) {
                const float d = ar[c][k] + 1e-8f;
                u[k] =  fmaxf(CLIPV - Wr[c][k], 0.f) / d;
                l[k] = -fmaxf(CLIPV + Wr[c][k], 0.f) / d;
            }
            *(float4*)(g_up + (size_t)i * Hn + j) = up;
            *(float4*)(g_lo + (size_t)i * Hn + j) = lo;
        }
    }

    float xw[2][4];
#pragma unroll
    for (int c = 0; c < 2; c++) {
        const float4 X = *(const float4*)(x2h_w + (size_t)i * Dn + c * 128 + jb);
        xw[c][0] = X.x; xw[c][1] = X.y; xw[c][2] = X.z; xw[c][3] = X.w;
    }
    const float bias = x2h_b[i] + h2h_b[i];
    const float sv   = sigmoidf_(tau_v[i]);
    const float se   = sigmoidf_(tau_e[i]);

    // Per-warp double-buffered dU tiles.
    // WRITE (cp.async) lane address: tileN_w + c*512 BYTES  (c*128 floats)
    // READ  (LDS)      lane address: tileNg  + c*128 floats — SAME layout.
    const uint32_t du_smem = (uint32_t)__cvta_generic_to_shared(du_tiles);
    const uint32_t tile0w = du_smem + ((warp * 2 + 0) * 512 + jb) * 4;
    const uint32_t tile1w = du_smem + ((warp * 2 + 1) * 512 + jb) * 4;
    float* tile0g = du_tiles + (warp * 2 + 0) * 512 + jb;
    float* tile1g = du_tiles + (warp * 2 + 1) * 512 + jb;

    const float* dUrow = dU + ((size_t)b0 * Hn + i) * Hn;  // row base for b0
    const size_t bstride = (size_t)Hn * Hn;                // next b, same i

    // prime the pipeline: rows 0 and 1
#pragma unroll
    for (int c = 0; c < 4; c++)
        cp_async16(tile0w + c * 512, dUrow + c * 128 + jb);
    cp_commit();
#pragma unroll
    for (int c = 0; c < 4; c++)
        cp_async16(tile1w + c * 512, dUrow + bstride + c * 128 + jb);
    cp_commit();

    for (int bb = 0; bb < TB1; bb++) {
        const int b = b0 + bb;
        cp_wait1();   // tile for row bb is ready

        const float* buf = (bb & 1) ? tile1g : tile0g;

        // consume du from smem (conflict-free 16B LDS per lane)
        float p0 = 0.f, p1 = 0.f, p2 = 0.f, p3 = 0.f;
#pragma unroll
        for (int c = 0; c < 4; c++) {
            const float4 D4 = *(const float4*)(buf + c * 128);
            const float4 H4 = *(const float4*)&sh_h[bb][c * 128 + jb];
            p0 = fmaf(fmaf(ar[c][0], D4.x, Wr[c][0]), H4.x, p0);
            p1 = fmaf(fmaf(ar[c][1], D4.y, Wr[c][1]), H4.y, p1);
            p2 = fmaf(fmaf(ar[c][2], D4.z, Wr[c][2]), H4.z, p2);
            p3 = fmaf(fmaf(ar[c][3], D4.w, Wr[c][3]), H4.w, p3);
        }
        // Wx part: x read straight from L1/L2 (64KB, hot)
#pragma unroll
        for (int c = 0; c < 2; c++) {
            const float4 X4 = __ldg((const float4*)(x + (size_t)b * Dn + c * 128 + jb));
            p0 = fmaf(xw[c][0], X4.x, p0);
            p1 = fmaf(xw[c][1], X4.y, p1);
            p2 = fmaf(xw[c][2], X4.z, p2);
            p3 = fmaf(xw[c][3], X4.w, p3);
        }

        float p = (p0 + p1) + (p2 + p3);
#pragma unroll
        for (int off = 16; off; off >>= 1)
            p += __shfl_xor_sync(0xffffffffu, p, off);
        // butterfly done -> the LDS reads of `buf` have provably completed
        // (p data-depends on them), so refilling the same buffer is safe.

        if (bb + 2 < TB1) {
            const uint32_t tw = (bb & 1) ? tile1w : tile0w;
            const float* g = dUrow + (size_t)(bb + 2) * bstride;
#pragma unroll
            for (int c = 0; c < 4; c++)
                cp_async16(tw + c * 512, g + c * 128 + jb);
        }
        cp_commit();  // always commit: uniform group accounting

        const float vb  = __ldg(v + (size_t)b * Hn + i);
        const float teS = __ldg(trace_e + (size_t)b * Hn + i);
        if (lane == 0) {
            const float dv  = p + bias;
            const float vn  = fmaf(sv, dv - vb, vb);
            const float nte = fmaf(se, sh_h[bb][i] - teS, teS);
            out[OFF_V   + (size_t)b * Hn + i] = vn;
            out[OFF_NH  + (size_t)b * Hn + i] = fmaxf(vn, 0.f);
            out[OFF_TEO + (size_t)b * Hn + i] = nte;
        }
    }
}

// ---------------------------------------------------------------------------
// P2: pure streaming elementwise pass over the HxH matrices.
// 4 independent tasks per thread; trace_E via __ldcs; outputs via __stcs.
// ---------------------------------------------------------------------------
#define P2_BLOCKS 4096
#define P2_THREADS 256
#define P2_TOTAL  ((size_t)Bn * Hn * 128)
#define P2_QTR    (P2_TOTAL / 4)

__global__ __launch_bounds__(P2_THREADS) void p2_kernel(
    const float* __restrict__ dU, const float* __restrict__ trace_E,
    const float* __restrict__ h, const float* __restrict__ trace_e,
    float* __restrict__ out) {
    const size_t gid = (size_t)blockIdx.x * P2_THREADS + threadIdx.x;
    const float sE  = g_sE;
    const float omU = g_omU;

    const float4* dU4 = (const float4*)dU;
    const float4* tE4 = (const float4*)trace_E;
    const float4* h4p = (const float4*)h;
    const float4* te4p = (const float4*)trace_e;
    const float4* up4 = (const float4*)g_up;
    const float4* lo4 = (const float4*)g_lo;
    float4* outDU = (float4*)(out + OFF_DU);
    float4* outTE = (float4*)(out + OFF_TEE);

#pragma unroll
    for (int q = 0; q < 4; q++) {
        const size_t t = gid + (size_t)q * P2_QTR;
        const int j4  = (int)(t & 127);
        const size_t row = t >> 7;           // b*512 + i
        const int i = (int)(row & 511);
        const int b = (int)(row >> 9);

        const float4 du = dU4[t];
        const float4 tE = __ldcs(&tE4[t]);
        const float4 hh = h4p[((size_t)b << 7) + j4];
        const float4 te = te4p[((size_t)b << 7) + j4];
        const float4 up = up4[((size_t)i << 7) + j4];
        const float4 lo = lo4[((size_t)i << 7) + j4];
        const float nh  = __ldg(out + OFF_NH  + row);
        const float nte = __ldg(out + OFF_TEO + row);
        const float suMod = g_suMod[b];

        float4 tOut, dOut;
        {
            const float o = nh * te.x - nte * hh.x;
            tOut.x = fmaf(sE, o - tE.x, tE.x);
            dOut.x = fmaxf(fminf(fmaf(suMod, tOut.x, omU * du.x), up.x), lo.x);
        }
        {
            const float o = nh * te.y - nte * hh.y;
            tOut.y = fmaf(sE, o - tE.y, tE.y);
            dOut.y = fmaxf(fminf(fmaf(suMod, tOut.y, omU * du.y), up.y), lo.y);
        }
        {
            const float o = nh * te.z - nte * hh.z;
            tOut.z = fmaf(sE, o - tE.z, tE.z);
            dOut.z = fmaxf(fminf(fmaf(suMod, tOut.z, omU * du.z), up.z), lo.z);
        }
        {
            const float o = nh * te.w - nte * hh.w;
            tOut.w = fmaf(sE, o - tE.w, tE.w);
            dOut.w = fmaxf(fminf(fmaf(suMod, tOut.w, omU * du.w), up.w), lo.w);
        }
        __stcs(&outTE[t], tOut);
        __stcs(&outDU[t], dOut);
    }
}

extern "C" void kernel_launch(void* const* d_in, const int* in_sizes, int n_in,
                              void* d_out, int out_size) {
    const float* x       = (const float*)d_in[0];
    const float* h       = (const float*)d_in[1];
    const float* v       = (const float*)d_in[2];
    const float* dU      = (const float*)d_in[3];
    const float* trace_e = (const float*)d_in[4];
    const float* trace_E = (const float*)d_in[5];
    const float* x2h_w   = (const float*)d_in[6];
    const float* x2h_b   = (const float*)d_in[7];
    const float* h2h_w   = (const float*)d_in[8];
    const float* h2h_b   = (const float*)d_in[9];
    const float* alpha   = (const float*)d_in[10];
    const float* tau_v   = (const float*)d_in[11];
    const float* tau_e   = (const float*)d_in[12];
    const float* tau_U   = (const float*)d_in[13];
    const float* tau_E   = (const float*)d_in[14];
    float* out = (float*)d_out;

    const int p1_smem = 12288 * 4;  // 48KB: 16KB du tiles + 32KB sh_h
    cudaFuncSetAttribute(p1_kernel,
                         cudaFuncAttributeMaxDynamicSharedMemorySize, p1_smem);
    p1_kernel<<<576, 128, p1_smem>>>(x, h, v, dU, trace_e, x2h_w, x2h_b,
                                     h2h_w, h2h_b, alpha, tau_v, tau_e,
                                     tau_U, tau_E, out);
    p2_kernel<<<P2_BLOCKS, P2_THREADS>>>(dU, trace_E, h, trace_e, out);
}